// round 6
// baseline (speedup 1.0000x reference)
#include <cuda_runtime.h>

#define HH 128
#define WW 128
#define CC 64
#define NHEAD 8
#define HD 8
#define NTOK 256
#define NTHREADS 128
#define GRID 1024
#define NUNITS 2048

// ---- f32x2 packed-math helpers (sm_103a) ----
__device__ __forceinline__ unsigned long long f2pack(float lo, float hi) {
    unsigned long long r;
    asm("mov.b64 %0, {%1,%2};" : "=l"(r) : "f"(lo), "f"(hi));
    return r;
}
__device__ __forceinline__ void f2unpack(unsigned long long a, float &lo, float &hi) {
    asm("mov.b64 {%0,%1}, %2;" : "=f"(lo), "=f"(hi) : "l"(a));
}
__device__ __forceinline__ unsigned long long ffma2(unsigned long long a,
                                                    unsigned long long b,
                                                    unsigned long long c) {
    unsigned long long r;
    asm("fma.rn.f32x2 %0, %1, %2, %3;" : "=l"(r) : "l"(a), "l"(b), "l"(c));
    return r;
}
__device__ __forceinline__ unsigned long long fadd2(unsigned long long a,
                                                    unsigned long long b) {
    unsigned long long r;
    asm("add.rn.f32x2 %0, %1, %2;" : "=l"(r) : "l"(a), "l"(b));
    return r;
}
__device__ __forceinline__ float ex2f(float x) {
    float y; asm("ex2.approx.f32 %0, %1;" : "=f"(y) : "f"(x)); return y;
}

struct ull2 { unsigned long long x, y; };
__device__ __forceinline__ ull2 lds128(const void* p) {
    ull2 r;
    asm("ld.shared.v2.u64 {%0,%1}, [%2];"
        : "=l"(r.x), "=l"(r.y) : "l"(__cvta_generic_to_shared(p)));
    return r;
}

// Persistent: grid=1024 CTAs, each handles 2 (batch, window, head) units.
// 128 threads; thread t owns tokens n=2t and n=2t+1 (h = t, both ws).
__global__ __launch_bounds__(NTHREADS, 7) void lepe_kernel(
    const float* __restrict__ temp,   // (B,3,C,H,W) fp32
    const float* __restrict__ convw,  // (C,1,3,3)
    const float* __restrict__ convb,  // (C,)
    float* __restrict__ out)          // (B, H*W, C)
{
    // K token-major, duplicated (k,k); rows padded to 10 float2 = 80B
    // (16B-aligned rows for LDS.128, STS conflict 8-way instead of 32-way)
    __shared__ __align__(16) float2 Kd2[NTOK][HD + 2];
    // V token-major, compact 32B rows (LDS.128-aligned)
    __shared__ __align__(16) float  Vrow[NTOK][HD];
    __shared__ float Wc[HD][9];
    __shared__ float Bc[HD];

    const int t = threadIdx.x;
    const size_t plane = (size_t)HH * WW;   // 16384
    // fold softmax scale (hd^-0.5) and log2(e) into Q
    const float C1 = 0.35355339059327373f * 1.4426950408889634f;

    for (int it = 0; it < NUNITS / GRID; it++) {
        const int u    = blockIdx.x + it * GRID;
        const int wi   = u & 63;
        const int head = (u >> 6) & 7;
        const int b    = u >> 9;

        const float* qb = temp + ((size_t)b * 3 + 0) * CC * plane;
        const float* kb = temp + ((size_t)b * 3 + 1) * CC * plane;
        const float* vb = temp + ((size_t)b * 3 + 2) * CC * plane;
        const int colw = 2 * wi;

        // ---- prologue: Q -> regs, K/V -> smem ----
        unsigned long long q01[HD];     // (q[n=2t][d], q[n=2t+1][d])
        {
            const size_t sp = (size_t)t * WW + colw;
            #pragma unroll
            for (int d = 0; d < HD; d++) {
                const int c = head * HD + d;
                const float2 qq = *(const float2*)(qb + c * plane + sp);
                q01[d] = f2pack(qq.x * C1, qq.y * C1);
                const float2 kk = *(const float2*)(kb + c * plane + sp);
                Kd2[2*t  ][d] = make_float2(kk.x, kk.x);
                Kd2[2*t+1][d] = make_float2(kk.y, kk.y);
                const float2 vv = *(const float2*)(vb + c * plane + sp);
                Vrow[2*t  ][d] = vv.x;
                Vrow[2*t+1][d] = vv.y;
            }
        }
        if (t < HD * 9) Wc[t / 9][t % 9] = convw[(head * HD + t / 9) * 9 + (t % 9)];
        if (t < HD)     Bc[t] = convb[head * HD + t];
        __syncthreads();

        unsigned long long o0[4], o1[4];   // rows n=2t, n=2t+1: 4 f32x2 accums over d
        #pragma unroll
        for (int c = 0; c < 4; c++) { o0[c] = 0ULL; o1[c] = 0ULL; }
        float l0 = 0.f, l1 = 0.f;

        // ---- main loop: online softmax (|s| small -> exp2 exact, no max) ----
        #pragma unroll 2
        for (int j = 0; j < NTOK; j++) {
            const ull2 k01 = lds128(&Kd2[j][0]);
            const ull2 k23 = lds128(&Kd2[j][2]);
            const ull2 k45 = lds128(&Kd2[j][4]);
            const ull2 k67 = lds128(&Kd2[j][6]);
            const ull2 va  = lds128(&Vrow[j][0]);
            const ull2 vc  = lds128(&Vrow[j][4]);

            unsigned long long sA = ffma2(q01[0], k01.x, 0ULL);
            unsigned long long sB = ffma2(q01[4], k45.x, 0ULL);
            sA = ffma2(q01[1], k01.y, sA);
            sB = ffma2(q01[5], k45.y, sB);
            sA = ffma2(q01[2], k23.x, sA);
            sB = ffma2(q01[6], k67.x, sB);
            sA = ffma2(q01[3], k23.y, sA);
            sB = ffma2(q01[7], k67.y, sB);
            const unsigned long long s01 = fadd2(sA, sB);

            float s0, s1;
            f2unpack(s01, s0, s1);
            const float p0 = ex2f(s0), p1 = ex2f(s1);
            l0 += p0; l1 += p1;

            const unsigned long long pp0 = f2pack(p0, p0);
            const unsigned long long pp1 = f2pack(p1, p1);
            o0[0] = ffma2(pp0, va.x, o0[0]);  o1[0] = ffma2(pp1, va.x, o1[0]);
            o0[1] = ffma2(pp0, va.y, o0[1]);  o1[1] = ffma2(pp1, va.y, o1[1]);
            o0[2] = ffma2(pp0, vc.x, o0[2]);  o1[2] = ffma2(pp1, vc.x, o1[2]);
            o0[3] = ffma2(pp0, vc.y, o0[3]);  o1[3] = ffma2(pp1, vc.y, o1[3]);
        }

        // ---- epilogue: normalize + fused depthwise 3x3 (LePE) + store ----
        const int h = t;
        #pragma unroll
        for (int r = 0; r < 2; r++) {
            const int ws = r;
            const float inv = 1.0f / (r == 0 ? l0 : l1);
            float ov[8];
            #pragma unroll
            for (int c = 0; c < 4; c++) {
                float lo, hi;
                f2unpack(r == 0 ? o0[c] : o1[c], lo, hi);
                ov[2*c] = lo * inv; ov[2*c+1] = hi * inv;
            }
            #pragma unroll
            for (int d = 0; d < HD; d++) {
                float acc = Bc[d];
                #pragma unroll
                for (int dh = -1; dh <= 1; dh++) {
                    const int hh = h + dh;
                    if (hh >= 0 && hh < HH) {
                        const float va  = Vrow[2*hh  ][d];   // ws' = 0
                        const float vb2 = Vrow[2*hh+1][d];   // ws' = 1
                        if (ws == 0)
                            acc += Wc[d][(dh+1)*3 + 1] * va + Wc[d][(dh+1)*3 + 2] * vb2;
                        else
                            acc += Wc[d][(dh+1)*3 + 0] * va + Wc[d][(dh+1)*3 + 1] * vb2;
                    }
                }
                ov[d] += acc;
            }
            const size_t ob = (((size_t)b * plane) + (size_t)h * WW + (colw + ws)) * CC
                              + (size_t)head * HD;
            float4* op = (float4*)(out + ob);
            op[0] = make_float4(ov[0], ov[1], ov[2], ov[3]);
            op[1] = make_float4(ov[4], ov[5], ov[6], ov[7]);
        }
        __syncthreads();   // protect smem before next unit's prologue
    }
}

extern "C" void kernel_launch(void* const* d_in, const int* in_sizes, int n_in,
                              void* d_out, int out_size) {
    const float* temp = (const float*)d_in[0];
    const float* cw   = (const float*)d_in[1];
    const float* cb   = (const float*)d_in[2];
    float* out        = (float*)d_out;
    (void)in_sizes; (void)n_in; (void)out_size;
    lepe_kernel<<<GRID, NTHREADS>>>(temp, cw, cb, out);
}

// round 7
// speedup vs baseline: 2.5047x; 2.5047x over previous
#include <cuda_runtime.h>
#include <cuda_fp16.h>

#define HH 128
#define WW 128
#define CC 64
#define HD 8
#define NTOK 256

__device__ __forceinline__ unsigned tf32c(float f) {
    unsigned r; asm("cvt.rna.tf32.f32 %0, %1;" : "=r"(r) : "f"(f)); return r;
}
__device__ __forceinline__ float ex2f(float x) {
    float y; asm("ex2.approx.f32 %0, %1;" : "=f"(y) : "f"(x)); return y;
}
__device__ __forceinline__ void mma_tf32(float d[4], const unsigned a[4], uint2 b) {
    asm("mma.sync.aligned.m16n8k8.row.col.f32.tf32.tf32.f32 "
        "{%0,%1,%2,%3}, {%4,%5,%6,%7}, {%8,%9}, {%0,%1,%2,%3};"
        : "+f"(d[0]), "+f"(d[1]), "+f"(d[2]), "+f"(d[3])
        : "r"(a[0]), "r"(a[1]), "r"(a[2]), "r"(a[3]), "r"(b.x), "r"(b.y));
}
__device__ __forceinline__ void mma_f16(float d[4], const unsigned a[4],
                                        unsigned b0, unsigned b1) {
    asm("mma.sync.aligned.m16n8k16.row.col.f32.f16.f16.f32 "
        "{%0,%1,%2,%3}, {%4,%5,%6,%7}, {%8,%9}, {%0,%1,%2,%3};"
        : "+f"(d[0]), "+f"(d[1]), "+f"(d[2]), "+f"(d[3])
        : "r"(a[0]), "r"(a[1]), "r"(a[2]), "r"(a[3]), "r"(b0), "r"(b1));
}
__device__ __forceinline__ unsigned packh2(float lo, float hi) {
    __half2 h = __floats2half2_rn(lo, hi);
    return *(unsigned*)&h;
}

// One CTA = one (batch, window, head). 128 threads = 4 warps.
// Warp w owns S/O rows 64w..64w+63 (4 m16 tiles).
__global__ __launch_bounds__(128, 4) void lepe_kernel(
    const float* __restrict__ temp,   // (B,3,C,H,W) fp32
    const float* __restrict__ convw,  // (C,1,3,3)
    const float* __restrict__ convb,  // (C,)
    float* __restrict__ out)          // (B,H*W,C)
{
    __shared__ __align__(16) float2 Qpair[NTOK][4];   // (q[c], q[c+4]), scaled by C1
    __shared__ __align__(16) uint2  KpairH[NTOK][4];  // tf32 hi, (c, c+4)
    __shared__ __align__(16) uint2  KpairL[NTOK][4];  // tf32 lo
    __shared__ unsigned Vh2u[HD][132];                // half2 over token pairs (pad: bank-spread)
    __shared__ float Vrow[NTOK][HD];                  // fp32 V for LePE conv
    __shared__ float Wc[HD][9];
    __shared__ float Bc[HD];

    const int wi   = blockIdx.x & 63;
    const int head = (blockIdx.x >> 6) & 7;
    const int b    = blockIdx.x >> 9;
    const int t    = threadIdx.x;
    const int lane = t & 31;
    const int w    = t >> 5;
    const int q4   = lane & 3;
    const int r4   = lane >> 2;

    const size_t plane = (size_t)HH * WW;
    const float* qb = temp + ((size_t)b * 3 + 0) * CC * plane;
    const float* kb = temp + ((size_t)b * 3 + 1) * CC * plane;
    const float* vb = temp + ((size_t)b * 3 + 2) * CC * plane;
    const int colw = 2 * wi;
    const float C1 = 0.35355339059327373f * 1.4426950408889634f; // hd^-0.5 * log2(e)

    // ---- prologue: thread t loads tokens 2t, 2t+1 ----
    {
        float qv0[8], qv1[8], kh0[8], kh1[8], kl0[8], kl1[8], v0[8], v1[8];
        const size_t sp = (size_t)t * WW + colw;
        #pragma unroll
        for (int d = 0; d < 8; d++) {
            const int c = head * 8 + d;
            const float2 qq = *(const float2*)(qb + c * plane + sp);
            qv0[d] = qq.x * C1; qv1[d] = qq.y * C1;
            const float2 kk = *(const float2*)(kb + c * plane + sp);
            kh0[d] = __uint_as_float(tf32c(kk.x));
            kh1[d] = __uint_as_float(tf32c(kk.y));
            kl0[d] = kk.x - kh0[d];
            kl1[d] = kk.y - kh1[d];
            const float2 vv = *(const float2*)(vb + c * plane + sp);
            v0[d] = vv.x; v1[d] = vv.y;
        }
        #pragma unroll
        for (int c = 0; c < 4; c++) {
            Qpair[2*t  ][c] = make_float2(qv0[c], qv0[c+4]);
            Qpair[2*t+1][c] = make_float2(qv1[c], qv1[c+4]);
            KpairH[2*t  ][c] = make_uint2(__float_as_uint(kh0[c]), __float_as_uint(kh0[c+4]));
            KpairH[2*t+1][c] = make_uint2(__float_as_uint(kh1[c]), __float_as_uint(kh1[c+4]));
            KpairL[2*t  ][c] = make_uint2(tf32c(kl0[c]), tf32c(kl0[c+4]));
            KpairL[2*t+1][c] = make_uint2(tf32c(kl1[c]), tf32c(kl1[c+4]));
        }
        #pragma unroll
        for (int d = 0; d < 8; d++) {
            Vh2u[d][t] = packh2(v0[d], v1[d]);
            Vrow[2*t  ][d] = v0[d];
            Vrow[2*t+1][d] = v1[d];
        }
    }
    if (t < 72) Wc[t/9][t%9] = convw[(head*8 + t/9)*9 + (t%9)];
    if (t < 8)  Bc[t] = convb[head*8 + t];
    __syncthreads();

    // ---- Q fragments (A of m16n8k8 tf32), split hi/lo, per m-tile ----
    unsigned QH[4][4], QL[4][4];
    #pragma unroll
    for (int mt = 0; mt < 4; mt++) {
        const int row0 = w*64 + mt*16 + r4;
        const float2 p0 = Qpair[row0    ][q4];   // (r, c), (r, c+4)
        const float2 p1 = Qpair[row0 + 8][q4];   // (r+8, c), (r+8, c+4)
        unsigned uh;
        uh = tf32c(p0.x); QH[mt][0] = uh; QL[mt][0] = tf32c(p0.x - __uint_as_float(uh));
        uh = tf32c(p1.x); QH[mt][1] = uh; QL[mt][1] = tf32c(p1.x - __uint_as_float(uh));
        uh = tf32c(p0.y); QH[mt][2] = uh; QL[mt][2] = tf32c(p0.y - __uint_as_float(uh));
        uh = tf32c(p1.y); QH[mt][3] = uh; QL[mt][3] = tf32c(p1.y - __uint_as_float(uh));
    }

    float O[4][4];
    float lp[4][2];
    #pragma unroll
    for (int mt = 0; mt < 4; mt++) {
        O[mt][0]=O[mt][1]=O[mt][2]=O[mt][3]=0.f;
        lp[mt][0]=lp[mt][1]=0.f;
    }

    // ---- main loop: 16 tokens per step (two jt8 S-tiles -> one k16 PV mma) ----
    for (int kt = 0; kt < 16; kt++) {
        const int tok0 = kt*16 + r4, tok1 = tok0 + 8;
        const uint2 bh0 = KpairH[tok0][q4], bh1 = KpairH[tok1][q4];
        const uint2 bl0 = KpairL[tok0][q4], bl1 = KpairL[tok1][q4];
        const unsigned bv0 = Vh2u[r4][kt*8 + q4];
        const unsigned bv1 = Vh2u[r4][kt*8 + 4 + q4];

        #pragma unroll
        for (int mt = 0; mt < 4; mt++) {
            float s0[4] = {0.f,0.f,0.f,0.f}, s1[4] = {0.f,0.f,0.f,0.f};
            mma_tf32(s0, QH[mt], bh0);
            mma_tf32(s0, QL[mt], bh0);
            mma_tf32(s0, QH[mt], bl0);
            mma_tf32(s1, QH[mt], bh1);
            mma_tf32(s1, QL[mt], bh1);
            mma_tf32(s1, QH[mt], bl1);

            const float e00 = ex2f(s0[0]), e01 = ex2f(s0[1]);
            const float e02 = ex2f(s0[2]), e03 = ex2f(s0[3]);
            const float e10 = ex2f(s1[0]), e11 = ex2f(s1[1]);
            const float e12 = ex2f(s1[2]), e13 = ex2f(s1[3]);
            lp[mt][0] += (e00 + e01) + (e10 + e11);   // row r
            lp[mt][1] += (e02 + e03) + (e12 + e13);   // row r+8

            unsigned a[4];
            a[0] = packh2(e00, e01);   // (r,   k 2q,2q+1)
            a[1] = packh2(e02, e03);   // (r+8, k 2q,2q+1)
            a[2] = packh2(e10, e11);   // (r,   k 8+2q,..)
            a[3] = packh2(e12, e13);   // (r+8, k 8+2q,..)
            mma_f16(O[mt], a, bv0, bv1);
        }
    }

    // ---- epilogue: row-sum reduce, normalize, LePE conv, store ----
    #pragma unroll
    for (int mt = 0; mt < 4; mt++) {
        #pragma unroll
        for (int rh = 0; rh < 2; rh++) {
            float l = lp[mt][rh];
            l += __shfl_xor_sync(0xffffffffu, l, 1);
            l += __shfl_xor_sync(0xffffffffu, l, 2);
            const float inv = 1.0f / l;
            const int n  = w*64 + mt*16 + rh*8 + r4;
            const int h  = n >> 1, ws = n & 1;
            const int d0 = 2*q4, d1 = d0 + 1;
            float o0 = O[mt][rh*2+0] * inv;
            float o1 = O[mt][rh*2+1] * inv;

            float acc0 = Bc[d0], acc1 = Bc[d1];
            #pragma unroll
            for (int dh = -1; dh <= 1; dh++) {
                const int hh2 = h + dh;
                if (hh2 >= 0 && hh2 < HH) {
                    const float va0 = Vrow[2*hh2][d0], vb0 = Vrow[2*hh2+1][d0];
                    const float va1 = Vrow[2*hh2][d1], vb1 = Vrow[2*hh2+1][d1];
                    const int bs = (dh+1)*3;
                    if (ws == 0) {
                        acc0 += Wc[d0][bs+1]*va0 + Wc[d0][bs+2]*vb0;
                        acc1 += Wc[d1][bs+1]*va1 + Wc[d1][bs+2]*vb1;
                    } else {
                        acc0 += Wc[d0][bs+0]*va0 + Wc[d0][bs+1]*vb0;
                        acc1 += Wc[d1][bs+0]*va1 + Wc[d1][bs+1]*vb1;
                    }
                }
            }
            o0 += acc0; o1 += acc1;

            const size_t ob = (((size_t)b * plane) + (size_t)h * WW + (colw + ws)) * CC
                              + (size_t)head * 8 + d0;
            *(float2*)(out + ob) = make_float2(o0, o1);
        }
    }
}

extern "C" void kernel_launch(void* const* d_in, const int* in_sizes, int n_in,
                              void* d_out, int out_size) {
    const float* temp = (const float*)d_in[0];
    const float* cw   = (const float*)d_in[1];
    const float* cb   = (const float*)d_in[2];
    float* out        = (float*)d_out;
    (void)in_sizes; (void)n_in; (void)out_size;
    lepe_kernel<<<4 * 64 * 8, 128>>>(temp, cw, cb, out);
}

// round 10
// speedup vs baseline: 2.5944x; 1.0358x over previous
#include <cuda_runtime.h>
#include <cuda_fp16.h>

#define HH 128
#define WW 128
#define CC 64
#define HD 8
#define NTOK 256

__device__ __forceinline__ unsigned tf32c(float f) {
    unsigned r; asm("cvt.rna.tf32.f32 %0, %1;" : "=r"(r) : "f"(f)); return r;
}
__device__ __forceinline__ float ex2f(float x) {
    float y; asm("ex2.approx.f32 %0, %1;" : "=f"(y) : "f"(x)); return y;
}
__device__ __forceinline__ void mma_tf32(float d[4], const unsigned a[4], uint2 b) {
    asm("mma.sync.aligned.m16n8k8.row.col.f32.tf32.tf32.f32 "
        "{%0,%1,%2,%3}, {%4,%5,%6,%7}, {%8,%9}, {%0,%1,%2,%3};"
        : "+f"(d[0]), "+f"(d[1]), "+f"(d[2]), "+f"(d[3])
        : "r"(a[0]), "r"(a[1]), "r"(a[2]), "r"(a[3]), "r"(b.x), "r"(b.y));
}
__device__ __forceinline__ void mma_f16(float d[4], const unsigned a[4],
                                        unsigned b0, unsigned b1) {
    asm("mma.sync.aligned.m16n8k16.row.col.f32.f16.f16.f32 "
        "{%0,%1,%2,%3}, {%4,%5,%6,%7}, {%8,%9}, {%0,%1,%2,%3};"
        : "+f"(d[0]), "+f"(d[1]), "+f"(d[2]), "+f"(d[3])
        : "r"(a[0]), "r"(a[1]), "r"(a[2]), "r"(a[3]), "r"(b0), "r"(b1));
}
__device__ __forceinline__ unsigned packh2(float lo, float hi) {
    __half2 h = __floats2half2_rn(lo, hi);
    return *(unsigned*)&h;
}

// One CTA = one (batch, window, head). 128 threads = 4 warps.
// Warp w owns S/O rows 64w..64w+63 (4 m16 tiles).
__global__ __launch_bounds__(128, 5) void lepe_kernel(
    const float* __restrict__ temp,   // (B,3,C,H,W) fp32
    const float* __restrict__ convw,  // (C,1,3,3)
    const float* __restrict__ convb,  // (C,)
    float* __restrict__ out)          // (B,H*W,C)
{
    __shared__ __align__(16) float2 Qpair[NTOK][4];   // (q[c], q[c+4]), scaled by C1
    __shared__ __align__(16) uint2  KpairH[NTOK][4];  // tf32(K), (c, c+4)
    __shared__ unsigned Vh2u[HD][132];                // half2 over token pairs (padded)
    __shared__ float Vrow[NTOK][HD];                  // fp32 V for LePE conv
    __shared__ float Wc[HD][9];
    __shared__ float Bc[HD];

    const int wi   = blockIdx.x & 63;
    const int head = (blockIdx.x >> 6) & 7;
    const int b    = blockIdx.x >> 9;
    const int t    = threadIdx.x;
    const int lane = t & 31;
    const int w    = t >> 5;
    const int q4   = lane & 3;
    const int r4   = lane >> 2;

    const size_t plane = (size_t)HH * WW;
    const float* qb = temp + ((size_t)b * 3 + 0) * CC * plane;
    const float* kb = temp + ((size_t)b * 3 + 1) * CC * plane;
    const float* vb = temp + ((size_t)b * 3 + 2) * CC * plane;
    const int colw = 2 * wi;
    const float C1 = 0.35355339059327373f * 1.4426950408889634f; // hd^-0.5 * log2(e)

    // ---- prologue: thread t loads tokens 2t, 2t+1 ----
    {
        const size_t sp = (size_t)t * WW + colw;
        #pragma unroll
        for (int d = 0; d < 8; d++) {
            const int c = head * 8 + d;
            const float2 vv = *(const float2*)(vb + c * plane + sp);
            Vh2u[d][t] = packh2(vv.x, vv.y);
            Vrow[2*t  ][d] = vv.x;
            Vrow[2*t+1][d] = vv.y;
        }
        float qv0[8], qv1[8], kk0[8], kk1[8];
        #pragma unroll
        for (int d = 0; d < 8; d++) {
            const int c = head * 8 + d;
            const float2 qq = *(const float2*)(qb + c * plane + sp);
            qv0[d] = qq.x * C1; qv1[d] = qq.y * C1;
            const float2 kk = *(const float2*)(kb + c * plane + sp);
            kk0[d] = kk.x; kk1[d] = kk.y;
        }
        #pragma unroll
        for (int c = 0; c < 4; c++) {
            Qpair[2*t  ][c] = make_float2(qv0[c], qv0[c+4]);
            Qpair[2*t+1][c] = make_float2(qv1[c], qv1[c+4]);
            KpairH[2*t  ][c] = make_uint2(tf32c(kk0[c]), tf32c(kk0[c+4]));
            KpairH[2*t+1][c] = make_uint2(tf32c(kk1[c]), tf32c(kk1[c+4]));
        }
    }
    if (t < 72) Wc[t/9][t%9] = convw[(head*8 + t/9)*9 + (t%9)];
    if (t < 8)  Bc[t] = convb[head*8 + t];
    __syncthreads();

    // ---- Q fragments (A of m16n8k8 tf32), split hi/lo, per m-tile ----
    unsigned QH[4][4], QL[4][4];
    #pragma unroll
    for (int mt = 0; mt < 4; mt++) {
        const int row0 = w*64 + mt*16 + r4;
        const float2 p0 = Qpair[row0    ][q4];   // (r, c), (r, c+4)
        const float2 p1 = Qpair[row0 + 8][q4];   // (r+8, c), (r+8, c+4)
        unsigned uh;
        uh = tf32c(p0.x); QH[mt][0] = uh; QL[mt][0] = tf32c(p0.x - __uint_as_float(uh));
        uh = tf32c(p1.x); QH[mt][1] = uh; QL[mt][1] = tf32c(p1.x - __uint_as_float(uh));
        uh = tf32c(p0.y); QH[mt][2] = uh; QL[mt][2] = tf32c(p0.y - __uint_as_float(uh));
        uh = tf32c(p1.y); QH[mt][3] = uh; QL[mt][3] = tf32c(p1.y - __uint_as_float(uh));
    }

    float O[4][4];
    float lp[4][2];
    #pragma unroll
    for (int mt = 0; mt < 4; mt++) {
        O[mt][0]=O[mt][1]=O[mt][2]=O[mt][3]=0.f;
        lp[mt][0]=lp[mt][1]=0.f;
    }

    // ---- main loop: 16 tokens per step (two n8 S-tiles -> one k16 PV mma) ----
    #pragma unroll 2
    for (int kt = 0; kt < 16; kt++) {
        const int tok0 = kt*16 + r4, tok1 = tok0 + 8;
        const uint2 bh0 = KpairH[tok0][q4], bh1 = KpairH[tok1][q4];
        const unsigned bv0 = Vh2u[r4][kt*8 + q4];
        const unsigned bv1 = Vh2u[r4][kt*8 + 4 + q4];

        #pragma unroll
        for (int mt = 0; mt < 4; mt++) {
            float s0[4] = {0.f,0.f,0.f,0.f}, s1[4] = {0.f,0.f,0.f,0.f};
            mma_tf32(s0, QH[mt], bh0);
            mma_tf32(s0, QL[mt], bh0);
            mma_tf32(s1, QH[mt], bh1);
            mma_tf32(s1, QL[mt], bh1);

            const float e00 = ex2f(s0[0]), e01 = ex2f(s0[1]);
            const float e02 = ex2f(s0[2]), e03 = ex2f(s0[3]);
            const float e10 = ex2f(s1[0]), e11 = ex2f(s1[1]);
            const float e12 = ex2f(s1[2]), e13 = ex2f(s1[3]);
            lp[mt][0] += (e00 + e01) + (e10 + e11);   // row r
            lp[mt][1] += (e02 + e03) + (e12 + e13);   // row r+8

            unsigned a[4];
            a[0] = packh2(e00, e01);   // (r,   k 2q,2q+1)
            a[1] = packh2(e02, e03);   // (r+8, k 2q,2q+1)
            a[2] = packh2(e10, e11);   // (r,   k 8+2q,..)
            a[3] = packh2(e12, e13);   // (r+8, k 8+2q,..)
            mma_f16(O[mt], a, bv0, bv1);
        }
    }

    // ---- epilogue: row-sum reduce, normalize, LePE conv, store ----
    #pragma unroll
    for (int mt = 0; mt < 4; mt++) {
        #pragma unroll
        for (int rh = 0; rh < 2; rh++) {
            float l = lp[mt][rh];
            l += __shfl_xor_sync(0xffffffffu, l, 1);
            l += __shfl_xor_sync(0xffffffffu, l, 2);
            const float inv = 1.0f / l;
            const int n  = w*64 + mt*16 + rh*8 + r4;
            const int h  = n >> 1, ws = n & 1;
            const int d0 = 2*q4, d1 = d0 + 1;
            float o0 = O[mt][rh*2+0] * inv;
            float o1 = O[mt][rh*2+1] * inv;

            float acc0 = Bc[d0], acc1 = Bc[d1];
            #pragma unroll
            for (int dh = -1; dh <= 1; dh++) {
                const int hh2 = h + dh;
                if (hh2 >= 0 && hh2 < HH) {
                    const float va0 = Vrow[2*hh2][d0], vb0 = Vrow[2*hh2+1][d0];
                    const float va1 = Vrow[2*hh2][d1], vb1 = Vrow[2*hh2+1][d1];
                    const int bs = (dh+1)*3;
                    if (ws == 0) {
                        acc0 += Wc[d0][bs+1]*va0 + Wc[d0][bs+2]*vb0;
                        acc1 += Wc[d1][bs+1]*va1 + Wc[d1][bs+2]*vb1;
                    } else {
                        acc0 += Wc[d0][bs+0]*va0 + Wc[d0][bs+1]*vb0;
                        acc1 += Wc[d1][bs+0]*va1 + Wc[d1][bs+1]*vb1;
                    }
                }
            }
            o0 += acc0; o1 += acc1;

            const size_t ob = (((size_t)b * plane) + (size_t)h * WW + (colw + ws)) * CC
                              + (size_t)head * 8 + d0;
            *(float2*)(out + ob) = make_float2(o0, o1);
        }
    }
}

extern "C" void kernel_launch(void* const* d_in, const int* in_sizes, int n_in,
                              void* d_out, int out_size) {
    const float* temp = (const float*)d_in[0];
    const float* cw   = (const float*)d_in[1];
    const float* cb   = (const float*)d_in[2];
    float* out        = (float*)d_out;
    (void)in_sizes; (void)n_in; (void)out_size;
    lepe_kernel<<<4 * 64 * 8, 128>>>(temp, cw, cb, out);
}

// round 11
// speedup vs baseline: 2.6730x; 1.0303x over previous
#include <cuda_runtime.h>
#include <cuda_fp16.h>

#define HH 128
#define WW 128
#define CC 64
#define HD 8
#define NTOK 256

__device__ __forceinline__ unsigned tf32c(float f) {
    unsigned r; asm("cvt.rna.tf32.f32 %0, %1;" : "=r"(r) : "f"(f)); return r;
}
__device__ __forceinline__ float ex2f(float x) {
    float y; asm("ex2.approx.f32 %0, %1;" : "=f"(y) : "f"(x)); return y;
}
__device__ __forceinline__ void mma_tf32(float d[4], const unsigned a[4], uint2 b) {
    asm("mma.sync.aligned.m16n8k8.row.col.f32.tf32.tf32.f32 "
        "{%0,%1,%2,%3}, {%4,%5,%6,%7}, {%8,%9}, {%0,%1,%2,%3};"
        : "+f"(d[0]), "+f"(d[1]), "+f"(d[2]), "+f"(d[3])
        : "r"(a[0]), "r"(a[1]), "r"(a[2]), "r"(a[3]), "r"(b.x), "r"(b.y));
}
__device__ __forceinline__ void mma_f16(float d[4], const unsigned a[4],
                                        unsigned b0, unsigned b1) {
    asm("mma.sync.aligned.m16n8k16.row.col.f32.f16.f16.f32 "
        "{%0,%1,%2,%3}, {%4,%5,%6,%7}, {%8,%9}, {%0,%1,%2,%3};"
        : "+f"(d[0]), "+f"(d[1]), "+f"(d[2]), "+f"(d[3])
        : "r"(a[0]), "r"(a[1]), "r"(a[2]), "r"(a[3]), "r"(b0), "r"(b1));
}
__device__ __forceinline__ unsigned packh2(float lo, float hi) {
    __half2 h = __floats2half2_rn(lo, hi);
    return *(unsigned*)&h;
}

// One CTA = one (batch, window, head). 256 threads = 8 warps.
// Warp w owns S/O rows 32w..32w+31 (2 m16 tiles).
__global__ __launch_bounds__(256, 3) void lepe_kernel(
    const float* __restrict__ temp,   // (B,3,C,H,W) fp32
    const float* __restrict__ convw,  // (C,1,3,3)
    const float* __restrict__ convb,  // (C,)
    float* __restrict__ out)          // (B,H*W,C)
{
    __shared__ __align__(16) float2 Qpair[NTOK][4];   // (q[c], q[c+4]), scaled by C1
    __shared__ __align__(16) uint2  KpairH[NTOK][4];  // tf32(K), (c, c+4)
    __shared__ unsigned Vh2u[HD][132];                // half2 over token pairs (padded)
    __shared__ float Vrow[NTOK][HD];                  // fp32 V for LePE conv
    __shared__ float Wc[HD][9];
    __shared__ float Bc[HD];

    const int wi   = blockIdx.x & 63;
    const int head = (blockIdx.x >> 6) & 7;
    const int b    = blockIdx.x >> 9;
    const int t    = threadIdx.x;
    const int lane = t & 31;
    const int w    = t >> 5;
    const int q4   = lane & 3;
    const int r4   = lane >> 2;

    const size_t plane = (size_t)HH * WW;
    const float* qb = temp + ((size_t)b * 3 + 0) * CC * plane;
    const float* kb = temp + ((size_t)b * 3 + 1) * CC * plane;
    const float* vb = temp + ((size_t)b * 3 + 2) * CC * plane;
    const int colw = 2 * wi;
    const float C1 = 0.35355339059327373f * 1.4426950408889634f; // hd^-0.5 * log2(e)

    // ---- prologue: thread (t0, h2) loads tokens 2t0, 2t0+1 for channel-pairs ----
    // h2=0 -> c in {0,1} (d {0,1,4,5});  h2=1 -> c in {2,3} (d {2,3,6,7})
    {
        const int t0 = t & 127;
        const int h2 = t >> 7;
        const size_t sp = (size_t)t0 * WW + colw;
        #pragma unroll
        for (int ci = 0; ci < 2; ci++) {
            const int c   = 2 * h2 + ci;       // pair slot
            const int dlo = c, dhi = c + 4;    // channels
            const float2 qlo = *(const float2*)(qb + (head*8 + dlo) * plane + sp);
            const float2 qhi = *(const float2*)(qb + (head*8 + dhi) * plane + sp);
            Qpair[2*t0  ][c] = make_float2(qlo.x * C1, qhi.x * C1);
            Qpair[2*t0+1][c] = make_float2(qlo.y * C1, qhi.y * C1);
            const float2 klo = *(const float2*)(kb + (head*8 + dlo) * plane + sp);
            const float2 khi = *(const float2*)(kb + (head*8 + dhi) * plane + sp);
            KpairH[2*t0  ][c] = make_uint2(tf32c(klo.x), tf32c(khi.x));
            KpairH[2*t0+1][c] = make_uint2(tf32c(klo.y), tf32c(khi.y));
            const float2 vlo = *(const float2*)(vb + (head*8 + dlo) * plane + sp);
            const float2 vhi = *(const float2*)(vb + (head*8 + dhi) * plane + sp);
            Vh2u[dlo][t0] = packh2(vlo.x, vlo.y);
            Vh2u[dhi][t0] = packh2(vhi.x, vhi.y);
            Vrow[2*t0  ][dlo] = vlo.x;  Vrow[2*t0+1][dlo] = vlo.y;
            Vrow[2*t0  ][dhi] = vhi.x;  Vrow[2*t0+1][dhi] = vhi.y;
        }
    }
    if (t < 72) Wc[t/9][t%9] = convw[(head*8 + t/9)*9 + (t%9)];
    if (t < 8)  Bc[t] = convb[head*8 + t];
    __syncthreads();

    // ---- Q fragments (A of m16n8k8 tf32), split hi/lo, per m-tile ----
    unsigned QH[2][4], QL[2][4];
    #pragma unroll
    for (int mt = 0; mt < 2; mt++) {
        const int row0 = w*32 + mt*16 + r4;
        const float2 p0 = Qpair[row0    ][q4];   // (r, c), (r, c+4)
        const float2 p1 = Qpair[row0 + 8][q4];   // (r+8, c), (r+8, c+4)
        unsigned uh;
        uh = tf32c(p0.x); QH[mt][0] = uh; QL[mt][0] = tf32c(p0.x - __uint_as_float(uh));
        uh = tf32c(p1.x); QH[mt][1] = uh; QL[mt][1] = tf32c(p1.x - __uint_as_float(uh));
        uh = tf32c(p0.y); QH[mt][2] = uh; QL[mt][2] = tf32c(p0.y - __uint_as_float(uh));
        uh = tf32c(p1.y); QH[mt][3] = uh; QL[mt][3] = tf32c(p1.y - __uint_as_float(uh));
    }

    float O[2][4];
    float lp[2][2];
    #pragma unroll
    for (int mt = 0; mt < 2; mt++) {
        O[mt][0]=O[mt][1]=O[mt][2]=O[mt][3]=0.f;
        lp[mt][0]=lp[mt][1]=0.f;
    }

    // ---- main loop: 16 tokens per step (two n8 S-tiles -> one k16 PV mma) ----
    #pragma unroll 2
    for (int kt = 0; kt < 16; kt++) {
        const int tok0 = kt*16 + r4, tok1 = tok0 + 8;
        const uint2 bh0 = KpairH[tok0][q4], bh1 = KpairH[tok1][q4];
        const unsigned bv0 = Vh2u[r4][kt*8 + q4];
        const unsigned bv1 = Vh2u[r4][kt*8 + 4 + q4];

        #pragma unroll
        for (int mt = 0; mt < 2; mt++) {
            float s0[4] = {0.f,0.f,0.f,0.f}, s1[4] = {0.f,0.f,0.f,0.f};
            mma_tf32(s0, QH[mt], bh0);
            mma_tf32(s0, QL[mt], bh0);
            mma_tf32(s1, QH[mt], bh1);
            mma_tf32(s1, QL[mt], bh1);

            const float e00 = ex2f(s0[0]), e01 = ex2f(s0[1]);
            const float e02 = ex2f(s0[2]), e03 = ex2f(s0[3]);
            const float e10 = ex2f(s1[0]), e11 = ex2f(s1[1]);
            const float e12 = ex2f(s1[2]), e13 = ex2f(s1[3]);
            lp[mt][0] += (e00 + e01) + (e10 + e11);   // row r
            lp[mt][1] += (e02 + e03) + (e12 + e13);   // row r+8

            unsigned a[4];
            a[0] = packh2(e00, e01);   // (r,   k 2q,2q+1)
            a[1] = packh2(e02, e03);   // (r+8, k 2q,2q+1)
            a[2] = packh2(e10, e11);   // (r,   k 8+2q,..)
            a[3] = packh2(e12, e13);   // (r+8, k 8+2q,..)
            mma_f16(O[mt], a, bv0, bv1);
        }
    }

    // ---- epilogue: row-sum reduce, normalize, LePE conv, store ----
    #pragma unroll
    for (int mt = 0; mt < 2; mt++) {
        #pragma unroll
        for (int rh = 0; rh < 2; rh++) {
            float l = lp[mt][rh];
            l += __shfl_xor_sync(0xffffffffu, l, 1);
            l += __shfl_xor_sync(0xffffffffu, l, 2);
            const float inv = 1.0f / l;
            const int n  = w*32 + mt*16 + rh*8 + r4;
            const int h  = n >> 1, ws = n & 1;
            const int d0 = 2*q4, d1 = d0 + 1;
            float o0 = O[mt][rh*2+0] * inv;
            float o1 = O[mt][rh*2+1] * inv;

            float acc0 = Bc[d0], acc1 = Bc[d1];
            #pragma unroll
            for (int dh = -1; dh <= 1; dh++) {
                const int hh2 = h + dh;
                if (hh2 >= 0 && hh2 < HH) {
                    const float va0 = Vrow[2*hh2][d0], vb0 = Vrow[2*hh2+1][d0];
                    const float va1 = Vrow[2*hh2][d1], vb1 = Vrow[2*hh2+1][d1];
                    const int bs = (dh+1)*3;
                    if (ws == 0) {
                        acc0 += Wc[d0][bs+1]*va0 + Wc[d0][bs+2]*vb0;
                        acc1 += Wc[d1][bs+1]*va1 + Wc[d1][bs+2]*vb1;
                    } else {
                        acc0 += Wc[d0][bs+0]*va0 + Wc[d0][bs+1]*vb0;
                        acc1 += Wc[d1][bs+0]*va1 + Wc[d1][bs+1]*vb1;
                    }
                }
            }
            o0 += acc0; o1 += acc1;

            const size_t ob = (((size_t)b * plane) + (size_t)h * WW + (colw + ws)) * CC
                              + (size_t)head * 8 + d0;
            *(float2*)(out + ob) = make_float2(o0, o1);
        }
    }
}

extern "C" void kernel_launch(void* const* d_in, const int* in_sizes, int n_in,
                              void* d_out, int out_size) {
    const float* temp = (const float*)d_in[0];
    const float* cw   = (const float*)d_in[1];
    const float* cb   = (const float*)d_in[2];
    float* out        = (float*)d_out;
    (void)in_sizes; (void)n_in; (void)out_size;
    lepe_kernel<<<4 * 64 * 8, 256>>>(temp, cw, cb, out);
}